// round 16
// baseline (speedup 1.0000x reference)
#include <cuda_runtime.h>

namespace {
constexpr int T_ = 1024;
constexpr int S_ = 512;
constexpr int D_ = 32;
constexpr int K_ = 64;
constexpr int G_ = 2;                 // split factor over the reduction dims
constexpr int NT_ = K_ * G_;          // 128 threads per block
constexpr float LOG2PI_F = 1.8378770664093453f;
constexpr float SHIFT = 72.0f;        // shift log-probs so per-step scale ~ O(1)
constexpr float LOG2E = 1.4426950408889634f;
}

// Per-sequence total log-denominator (fp64 for the stable cross-sequence sum).
__device__ double g_logden[S_];

// ---- packed f32x2 helpers (sm_103a dual-lane fp32 pipe) ----
__device__ __forceinline__ unsigned long long fma2(unsigned long long a,
                                                   unsigned long long b,
                                                   unsigned long long c) {
    unsigned long long d;
    asm("fma.rn.f32x2 %0, %1, %2, %3;" : "=l"(d) : "l"(a), "l"(b), "l"(c));
    return d;
}
__device__ __forceinline__ unsigned long long add2(unsigned long long a,
                                                   unsigned long long b) {
    unsigned long long d;
    asm("add.rn.f32x2 %0, %1, %2;" : "=l"(d) : "l"(a), "l"(b));
    return d;
}
__device__ __forceinline__ unsigned long long pack2(float lo, float hi) {
    unsigned long long v;
    unsigned int l = __float_as_uint(lo), h = __float_as_uint(hi);
    asm("mov.b64 %0, {%1, %2};" : "=l"(v) : "r"(l), "r"(h));
    return v;
}
__device__ __forceinline__ float hsum2(unsigned long long v) {
    unsigned int l, h;
    asm("mov.b64 {%0, %1}, %2;" : "=r"(l), "=r"(h) : "l"(v));
    return __uint_as_float(l) + __uint_as_float(h);
}

__global__ void __launch_bounds__(NT_) hmm_forward_kernel(
    const float* __restrict__ data,     // [T, S, D]
    const float* __restrict__ initp,    // [K]
    const float* __restrict__ trans,    // [K, K] row-stochastic
    const float* __restrict__ means,    // [K, D]
    const float* __restrict__ covars,   // [K, D]
    float* __restrict__ out)            // [S, K] alpha (+ scalar)
{
    const int s   = blockIdx.x;
    const int tid = threadIdx.x;
    const int k   = tid & (K_ - 1);     // state
    const int g   = tid >> 6;           // slice (0 or 1)

    __shared__ __align__(16) float  buf[K_];       // unnormalized alpha
    __shared__ __align__(16) float4 me[K_];        // {m_g0, e_g0, m_g1, e_g1}
    __shared__ __align__(16) float  dsh[4];        // d partials per slice
    __shared__ __align__(16) float  xsh[2][D_];    // double-buffered observation

    // ---- per-state Gaussian constants (in log2 space) ----
    // log2 p_k(x) = sum_d x*(c1*x + c2) + ck2 ; c1 = -0.5*log2e/cov, c2 = mu*log2e/cov
    // this thread handles dims [16g, 16g+16); ck2 uses the full row (once).
    const int dbase = g * (D_ / G_);
    unsigned long long c1p[D_ / G_ / 2], c2p[D_ / G_ / 2];
    float sq = 0.f, ld = 0.f;
#pragma unroll
    for (int q = 0; q < D_ / 4; ++q) {
        float4 mv = reinterpret_cast<const float4*>(means  + k * D_)[q];
        float4 cv = reinterpret_cast<const float4*>(covars + k * D_)[q];
        float i0 = 1.f / cv.x, i1 = 1.f / cv.y, i2 = 1.f / cv.z, i3 = 1.f / cv.w;
        sq += mv.x * mv.x * i0 + mv.y * mv.y * i1 + mv.z * mv.z * i2 + mv.w * mv.w * i3;
        ld += __logf(cv.x) + __logf(cv.y) + __logf(cv.z) + __logf(cv.w);
        int d0 = 4 * q - dbase;                       // position within my slice
        if (d0 >= 0 && d0 < D_ / G_) {
            c1p[d0 / 2 + 0] = pack2(-0.5f * LOG2E * i0, -0.5f * LOG2E * i1);
            c1p[d0 / 2 + 1] = pack2(-0.5f * LOG2E * i2, -0.5f * LOG2E * i3);
            c2p[d0 / 2 + 0] = pack2(mv.x * i0 * LOG2E, mv.y * i1 * LOG2E);
            c2p[d0 / 2 + 1] = pack2(mv.z * i2 * LOG2E, mv.w * i3 * LOG2E);
        }
    }
    const float ck2 = (-0.5f * (sq + ld + (float)D_ * LOG2PI_F) + SHIFT) * LOG2E;

    // Transition column slice: j in [32g, 32g+32), Ap[i] = (A[j0+2i][k], A[j0+2i+1][k])
    unsigned long long Ap[K_ / G_ / 2];
    const int jbase = g * (K_ / G_);
#pragma unroll
    for (int i = 0; i < K_ / G_ / 2; ++i)
        Ap[i] = pack2(__ldg(trans + (jbase + 2 * i) * K_ + k),
                      __ldg(trans + (jbase + 2 * i + 1) * K_ + k));

    // emission partial: log2-prob contribution of my 16 dims (+ck2 for g==0)
    auto emit_part = [&](const float* xs) -> float {
        const ulonglong2* x2 = reinterpret_cast<const ulonglong2*>(xs + dbase);
        unsigned long long e0 = (g == 0) ? pack2(ck2, 0.f) : 0ULL, e1 = 0ULL;
#pragma unroll
        for (int i = 0; i < D_ / G_ / 4; ++i) {
            ulonglong2 xv = x2[i];
            unsigned long long t0 = fma2(c1p[2 * i + 0], xv.x, c2p[2 * i + 0]);
            unsigned long long t1 = fma2(c1p[2 * i + 1], xv.y, c2p[2 * i + 1]);
            e0 = fma2(xv.x, t0, e0);
            e1 = fma2(xv.y, t1, e1);
        }
        return hsum2(add2(e0, e1));
    };

    // matvec partial over my 32 j's: m_part and d_part (sum of a_j)
    auto matvec_part = [&](float& mp, float& dp) {
        const ulonglong2* b2 = reinterpret_cast<const ulonglong2*>(buf + jbase);
        unsigned long long m0 = 0ULL, m1 = 0ULL, d0 = 0ULL, d1 = 0ULL;
#pragma unroll
        for (int i = 0; i < K_ / G_ / 4; ++i) {
            ulonglong2 av = b2[i];
            m0 = fma2(av.x, Ap[2 * i + 0], m0);
            m1 = fma2(av.y, Ap[2 * i + 1], m1);
            d0 = add2(d0, av.x);
            d1 = add2(d1, av.y);
        }
        mp = hsum2(add2(m0, m1));
        dp = hsum2(add2(d0, d1));
    };

    // ---- t = 0 (peeled): a_0 = p_0 * initp, unnormalized ----
    if (tid < D_ / 4)
        reinterpret_cast<uint4*>(xsh[0])[tid] =
            reinterpret_cast<const uint4*>(data + (size_t)s * D_)[tid];
    const float ipk = initp[k];
    __syncthreads();

    float alast;
    {
        float ep = emit_part(xsh[0]);
        reinterpret_cast<float2*>(&me[k])[g] =
            make_float2((g == 0) ? ipk : 0.f, ep);
        if (tid < D_ / 4)
            reinterpret_cast<uint4*>(xsh[1])[tid] =
                reinterpret_cast<const uint4*>(data + ((size_t)S_ + s) * D_)[tid];
        __syncthreads();
        float4 v = me[k];
        alast = exp2f(v.y + v.w) * (v.x + v.z);
        if (g == 0) buf[k] = alast;
        __syncthreads();
    }

    float  fll = 0.f;
    double dll = 0.0;

    for (int t = 1; t < T_; ++t) {
        // prefetch x_{t+1} (clamped)
        uint4 gx;
        if (tid < D_ / 4) {
            int tp = (t + 1 < T_) ? t + 1 : T_ - 1;
            gx = reinterpret_cast<const uint4*>(data + ((size_t)tp * S_ + s) * D_)[tid];
        }

        // phase 1: partials
        float mp, dp;
        matvec_part(mp, dp);                       // from buf (a_{t-1}), d = d_{t-1}
        float ep = emit_part(xsh[t & 1]);          // emission log2-prob for time t
        reinterpret_cast<float2*>(&me[k])[g] = make_float2(mp, ep);
        if (k == 0) dsh[g] = dp;
        if (tid < D_ / 4)
            reinterpret_cast<uint4*>(xsh[(t + 1) & 1])[tid] = gx;
        __syncthreads();

        // phase 2: combine
        float4 v = me[k];
        float m = v.x + v.z;
        float e = v.y + v.w;
        float d = dsh[0] + dsh[1];
        float p = exp2f(e);
        float rinv = __fdividef(1.0f, d);
        alast = p * m * rinv;                      // unnormalized a_t (prev d divided out)
        if (g == 0) buf[k] = alast;
        if (tid == 0) {
            fll += __logf(d);
            if ((t & 31) == 0) { dll += (double)fll; fll = 0.f; }
        }
        __syncthreads();
    }

    // ---- epilogue: d over final buf, normalize, finish log-denominator ----
    {
        const ulonglong2* b2 = reinterpret_cast<const ulonglong2*>(buf + jbase);
        unsigned long long d0 = 0ULL, d1 = 0ULL;
#pragma unroll
        for (int i = 0; i < K_ / G_ / 4; ++i) {
            ulonglong2 av = b2[i];
            d0 = add2(d0, av.x);
            d1 = add2(d1, av.y);
        }
        if (k == 0) dsh[g] = hsum2(add2(d0, d1));
        __syncthreads();
        float d = dsh[0] + dsh[1];
        if (g == 0)
            out[(size_t)s * K_ + k] = alast * __fdividef(1.0f, d);
        if (tid == 0) {
            fll += __logf(d);
            dll += (double)fll;
            dll -= (double)SHIFT * (double)T_;
            g_logden[s] = dll;
        }
    }
}

// Deterministic final reduction: nll = -sum_s logden[s]
__global__ void hmm_reduce_kernel(float* __restrict__ out, int out_size)
{
    __shared__ double sh[S_];
    int t = threadIdx.x;
    sh[t] = g_logden[t];
    __syncthreads();
#pragma unroll
    for (int off = S_ / 2; off > 0; off >>= 1) {
        if (t < off) sh[t] += sh[t + off];
        __syncthreads();
    }
    if (t == 0 && out_size > S_ * K_)
        out[S_ * K_] = (float)(-sh[0]);
}

extern "C" void kernel_launch(void* const* d_in, const int* in_sizes, int n_in,
                              void* d_out, int out_size)
{
    const float* data   = (const float*)d_in[0];
    const float* initp  = (const float*)d_in[1];
    const float* trans  = (const float*)d_in[2];
    const float* means  = (const float*)d_in[3];
    const float* covars = (const float*)d_in[4];
    float* out = (float*)d_out;

    hmm_forward_kernel<<<S_, NT_>>>(data, initp, trans, means, covars, out);
    hmm_reduce_kernel<<<1, S_>>>(out, out_size);
}

// round 17
// speedup vs baseline: 1.0344x; 1.0344x over previous
#include <cuda_runtime.h>

namespace {
constexpr int T_ = 1024;
constexpr int S_ = 512;
constexpr int D_ = 32;
constexpr int K_ = 64;
constexpr int G_ = 2;                  // split factor over reduction dims
constexpr int NT_ = K_ * G_;           // 128 threads per block
constexpr int STAGES_ = 6;             // x prefetch ring depth
constexpr int LOOKAHEAD_ = 5;          // cp.async lookahead (steps)
constexpr float LOG2PI_F = 1.8378770664093453f;
constexpr float SHIFT = 72.0f;         // shift log-probs so per-step scale ~ O(1)
constexpr float LOG2E = 1.4426950408889634f;
}

__device__ double g_logden[S_];
__device__ unsigned int g_count = 0;   // last-block election; reset each run

// ---- packed f32x2 helpers (sm_103a dual-lane fp32 pipe) ----
__device__ __forceinline__ unsigned long long fma2(unsigned long long a,
                                                   unsigned long long b,
                                                   unsigned long long c) {
    unsigned long long d;
    asm("fma.rn.f32x2 %0, %1, %2, %3;" : "=l"(d) : "l"(a), "l"(b), "l"(c));
    return d;
}
__device__ __forceinline__ unsigned long long add2(unsigned long long a,
                                                   unsigned long long b) {
    unsigned long long d;
    asm("add.rn.f32x2 %0, %1, %2;" : "=l"(d) : "l"(a), "l"(b));
    return d;
}
__device__ __forceinline__ unsigned long long pack2(float lo, float hi) {
    unsigned long long v;
    unsigned int l = __float_as_uint(lo), h = __float_as_uint(hi);
    asm("mov.b64 %0, {%1, %2};" : "=l"(v) : "r"(l), "r"(h));
    return v;
}
__device__ __forceinline__ float hsum2(unsigned long long v) {
    unsigned int l, h;
    asm("mov.b64 {%0, %1}, %2;" : "=r"(l), "=r"(h) : "l"(v));
    return __uint_as_float(l) + __uint_as_float(h);
}

// ---- cp.async helpers ----
__device__ __forceinline__ void cp_async16(unsigned int saddr, const void* gptr) {
    asm volatile("cp.async.cg.shared.global [%0], [%1], 16;"
                 :: "r"(saddr), "l"(gptr));
}
__device__ __forceinline__ void cp_commit() {
    asm volatile("cp.async.commit_group;" ::: "memory");
}
template <int N>
__device__ __forceinline__ void cp_wait() {
    asm volatile("cp.async.wait_group %0;" :: "n"(N) : "memory");
}

__global__ void __launch_bounds__(NT_) hmm_forward_kernel(
    const float* __restrict__ data,     // [T, S, D]
    const float* __restrict__ initp,    // [K]
    const float* __restrict__ trans,    // [K, K] row-stochastic
    const float* __restrict__ means,    // [K, D]
    const float* __restrict__ covars,   // [K, D]
    float* __restrict__ out,            // [S*K alphas][1 scalar]
    int out_size)
{
    const int s   = blockIdx.x;
    const int tid = threadIdx.x;
    const int k   = tid & (K_ - 1);     // state
    const int g   = tid >> 6;           // slice (0 or 1)

    __shared__ __align__(16) float  buf[K_];             // unnormalized alpha
    __shared__ __align__(16) float4 me[K_];              // {m_g0, e_g0, m_g1, e_g1}
    __shared__ __align__(16) float  dsh[2];              // d partials per slice
    __shared__ __align__(16) float  xsh[STAGES_][D_];    // prefetch ring

    // ---- per-state Gaussian constants for MY 16 dims (log2 space, static idx) ----
    const int dbase = g * (D_ / G_);
    unsigned long long c1p[D_ / G_ / 2], c2p[D_ / G_ / 2];
    float sq = 0.f, ld = 0.f;
#pragma unroll
    for (int q = 0; q < D_ / G_ / 4; ++q) {
        float4 mv = reinterpret_cast<const float4*>(means  + k * D_ + dbase)[q];
        float4 cv = reinterpret_cast<const float4*>(covars + k * D_ + dbase)[q];
        float i0 = 1.f / cv.x, i1 = 1.f / cv.y, i2 = 1.f / cv.z, i3 = 1.f / cv.w;
        c1p[2*q + 0] = pack2(-0.5f * LOG2E * i0, -0.5f * LOG2E * i1);
        c1p[2*q + 1] = pack2(-0.5f * LOG2E * i2, -0.5f * LOG2E * i3);
        c2p[2*q + 0] = pack2(mv.x * i0 * LOG2E, mv.y * i1 * LOG2E);
        c2p[2*q + 1] = pack2(mv.z * i2 * LOG2E, mv.w * i3 * LOG2E);
        sq += mv.x * mv.x * i0 + mv.y * mv.y * i1 + mv.z * mv.z * i2 + mv.w * mv.w * i3;
        ld += __logf(cv.x) + __logf(cv.y) + __logf(cv.z) + __logf(cv.w);
    }
    // half of the constant per slice; SHIFT carried by slice 0 only
    const float ck2 = -0.5f * LOG2E * (sq + ld + (float)(D_ / G_) * LOG2PI_F)
                    + ((g == 0) ? SHIFT * LOG2E : 0.f);

    // Transition column slice: j in [32g, 32g+32)
    const int jbase = g * (K_ / G_);
    unsigned long long Ap[K_ / G_ / 2];
#pragma unroll
    for (int i = 0; i < K_ / G_ / 2; ++i)
        Ap[i] = pack2(__ldg(trans + (jbase + 2 * i) * K_ + k),
                      __ldg(trans + (jbase + 2 * i + 1) * K_ + k));

    auto emit_part = [&](const float* xs) -> float {
        const ulonglong2* x2 = reinterpret_cast<const ulonglong2*>(xs + dbase);
        unsigned long long e0 = pack2(ck2, 0.f), e1 = 0ULL;
#pragma unroll
        for (int i = 0; i < D_ / G_ / 4; ++i) {
            ulonglong2 xv = x2[i];
            unsigned long long t0 = fma2(c1p[2 * i + 0], xv.x, c2p[2 * i + 0]);
            unsigned long long t1 = fma2(c1p[2 * i + 1], xv.y, c2p[2 * i + 1]);
            e0 = fma2(xv.x, t0, e0);
            e1 = fma2(xv.y, t1, e1);
        }
        return hsum2(add2(e0, e1));
    };

    auto matvec_part = [&](float& mp, float& dp) {
        const ulonglong2* b2 = reinterpret_cast<const ulonglong2*>(buf + jbase);
        unsigned long long m0 = 0ULL, m1 = 0ULL, d0 = 0ULL, d1 = 0ULL;
#pragma unroll
        for (int i = 0; i < K_ / G_ / 4; ++i) {
            ulonglong2 av = b2[i];
            m0 = fma2(av.x, Ap[2 * i + 0], m0);
            m1 = fma2(av.y, Ap[2 * i + 1], m1);
            d0 = add2(d0, av.x);
            d1 = add2(d1, av.y);
        }
        mp = hsum2(add2(m0, m1));
        dp = hsum2(add2(d0, d1));
    };

    // ---- cp.async prefetch ring: threads 0..7 each own one 16B chunk per stage ----
    unsigned int xbase = (unsigned int)__cvta_generic_to_shared(xsh);
    auto issue_x = [&](int tm) {   // copy x_tm into slot tm % STAGES_
        cp_async16(xbase + (unsigned)((tm % STAGES_) * D_ + tid * 4) * 4u,
                   data + ((size_t)tm * S_ + s) * D_ + tid * 4);
    };
    if (tid < D_ / 4) {
#pragma unroll
        for (int p = 0; p < LOOKAHEAD_; ++p) { issue_x(p); cp_commit(); }
    }

    const float ipk = initp[k];

    // ---- t = 0 (peeled): a_0 = p_0 * initp, unnormalized ----
    float alast;
    {
        if (tid < D_ / 4) { issue_x(LOOKAHEAD_); cp_commit(); cp_wait<4>(); }
        __syncthreads();                      // x_0 (and x_1) visible
        float ep = emit_part(xsh[0]);
        reinterpret_cast<float2*>(&me[k])[g] =
            make_float2((g == 0) ? ipk : 0.f, ep);
        __syncthreads();
        float4 v = me[k];
        alast = exp2f(v.y + v.w) * (v.x + v.z);
        if (g == 0) buf[k] = alast;
        __syncthreads();
    }

    float  fll = 0.f;
    double dll = 0.0;

    for (int t = 1; t < T_; ++t) {
        // keep the pipeline fed: one commit-group per step (empty at the tail)
        if (tid < D_ / 4) {
            int tp = t + LOOKAHEAD_;
            if (tp < T_) issue_x(tp);
            cp_commit();
        }

        // phase 1: partials
        float mp, dp;
        matvec_part(mp, dp);                        // from a_{t-1}; dp -> d_{t-1}
        float ep = emit_part(xsh[t % STAGES_]);     // log2 emission for time t
        reinterpret_cast<float2*>(&me[k])[g] = make_float2(mp, ep);
        if (k == 0) dsh[g] = dp;
        if (tid < D_ / 4) cp_wait<4>();             // x_{t+1} landed
        __syncthreads();

        // phase 2: combine
        float4 v = me[k];
        float m = v.x + v.z;
        float e = v.y + v.w;
        float d = dsh[0] + dsh[1];
        alast = exp2f(e) * m * __fdividef(1.0f, d); // unnormalized a_t
        if (g == 0) buf[k] = alast;
        if (tid == 0) {
            fll += __logf(d);
            if ((t & 31) == 0) { dll += (double)fll; fll = 0.f; }
        }
        __syncthreads();
    }

    // ---- epilogue: final d, normalize alpha, finish per-sequence log-denominator ----
    {
        const ulonglong2* b2 = reinterpret_cast<const ulonglong2*>(buf + jbase);
        unsigned long long d0 = 0ULL, d1 = 0ULL;
#pragma unroll
        for (int i = 0; i < K_ / G_ / 4; ++i) {
            ulonglong2 av = b2[i];
            d0 = add2(d0, av.x);
            d1 = add2(d1, av.y);
        }
        if (k == 0) dsh[g] = hsum2(add2(d0, d1));
        __syncthreads();
        float d = dsh[0] + dsh[1];
        if (g == 0)
            out[(size_t)s * K_ + k] = alast * __fdividef(1.0f, d);
        if (tid == 0) {
            fll += __logf(d);
            dll += (double)fll;
            dll -= (double)SHIFT * (double)T_;
            g_logden[s] = dll;
        }
    }

    // ---- last block folds the cross-sequence sum (deterministic order) ----
    __shared__ unsigned int lastv;
    if (tid == 0) {
        __threadfence();
        lastv = atomicAdd(&g_count, 1u);
    }
    __syncthreads();
    if (lastv == S_ - 1) {
        __shared__ double sh[NT_];
        double acc = 0.0;
#pragma unroll
        for (int i = 0; i < S_ / NT_; ++i)
            acc += g_logden[tid + i * NT_];
        sh[tid] = acc;
        __syncthreads();
#pragma unroll
        for (int off = NT_ / 2; off > 0; off >>= 1) {
            if (tid < off) sh[tid] += sh[tid + off];
            __syncthreads();
        }
        if (tid == 0) {
            if (out_size > S_ * K_) out[S_ * K_] = (float)(-sh[0]);
            g_count = 0;                    // reset for next graph replay
        }
    }
}

extern "C" void kernel_launch(void* const* d_in, const int* in_sizes, int n_in,
                              void* d_out, int out_size)
{
    const float* data   = (const float*)d_in[0];
    const float* initp  = (const float*)d_in[1];
    const float* trans  = (const float*)d_in[2];
    const float* means  = (const float*)d_in[3];
    const float* covars = (const float*)d_in[4];
    float* out = (float*)d_out;

    hmm_forward_kernel<<<S_, NT_>>>(data, initp, trans, means, covars, out, out_size);
}